// round 1
// baseline (speedup 1.0000x reference)
#include <cuda_runtime.h>
#include <cuda_bf16.h>
#include <stdint.h>

// ============================================================================
// LocalGNNBranch: 3-layer GraphSAGE, N=100k nodes, E=1.6M edges, D=64, B=64.
// Strategy:
//   - Build CSR (dst -> list of src) once per launch: histogram + 2-level
//     exclusive scan + atomic-cursor fill. Int atomics only.
//   - 3x [aggregation (gather, no float atomics) -> fused GEMM+bias+L2norm+ReLU]
//   - Sum-pool per graph via binary search on sorted batch ids (no atomics).
// All fp32. Everything stays L2-resident (~58MB hot set vs 126MB L2).
// ============================================================================

#define MAXN 100000
#define MAXE 1600000
#define DF   64          // feature dim
#define KK   128         // GEMM K = 2*DF (mean || x)
#define NT   32          // nodes per GEMM block
#define SCAN_CHUNK 1024
#define MAXBLK 128       // >= ceil(MAXN/SCAN_CHUNK) = 98

// ---- static device scratch (no allocation allowed) ----
__device__ float g_mean[(size_t)MAXN * DF];
__device__ float g_h1[(size_t)MAXN * DF];
__device__ float g_h2[(size_t)MAXN * DF];
__device__ int   g_deg[MAXN];
__device__ int   g_rowstart[MAXN];
__device__ int   g_cursor[MAXN];
__device__ int   g_csr[MAXE];
__device__ int   g_bsum[MAXBLK];
__device__ int   g_bsumex[MAXBLK];

// ---------------------------------------------------------------------------
__global__ void k_zero(int n) {
    int i = blockIdx.x * blockDim.x + threadIdx.x;
    if (i < n) { g_deg[i] = 0; g_cursor[i] = 0; }
}

__global__ void k_hist(const int* __restrict__ dst, int e) {
    int i = blockIdx.x * blockDim.x + threadIdx.x;
    if (i < e) atomicAdd(&g_deg[dst[i]], 1);
}

__global__ void k_blocksum(int n) {
    __shared__ int s[256];
    int tid = threadIdx.x;
    int start = blockIdx.x * SCAN_CHUNK;
    int end = min(start + SCAN_CHUNK, n);
    int sum = 0;
    for (int i = start + tid; i < end; i += 256) sum += g_deg[i];
    s[tid] = sum;
    __syncthreads();
    for (int d = 128; d > 0; d >>= 1) {
        if (tid < d) s[tid] += s[tid + d];
        __syncthreads();
    }
    if (tid == 0) g_bsum[blockIdx.x] = s[0];
}

__global__ void k_scan_bsums(int nblk) {
    if (threadIdx.x == 0 && blockIdx.x == 0) {
        int run = 0;
        for (int i = 0; i < nblk; i++) {
            int t = g_bsum[i];
            g_bsumex[i] = run;
            run += t;
        }
    }
}

__global__ void k_scan_final(int n) {
    __shared__ int s[256];
    int tid = threadIdx.x;
    int b = blockIdx.x;
    int base = b * SCAN_CHUNK + tid * 4;
    int v[4];
    int tsum = 0;
#pragma unroll
    for (int i = 0; i < 4; i++) {
        int gi = base + i;
        v[i] = (gi < n) ? g_deg[gi] : 0;
        tsum += v[i];
    }
    s[tid] = tsum;
    __syncthreads();
    for (int d = 1; d < 256; d <<= 1) {
        int t = (tid >= d) ? s[tid - d] : 0;
        __syncthreads();
        s[tid] += t;
        __syncthreads();
    }
    int excl = s[tid] - tsum;
    int run = g_bsumex[b] + excl;
#pragma unroll
    for (int i = 0; i < 4; i++) {
        int gi = base + i;
        if (gi < n) { g_rowstart[gi] = run; run += v[i]; }
    }
}

__global__ void k_fill(const int* __restrict__ src, const int* __restrict__ dst, int e) {
    int i = blockIdx.x * blockDim.x + threadIdx.x;
    if (i < e) {
        int d = dst[i];
        int p = atomicAdd(&g_cursor[d], 1);
        g_csr[g_rowstart[d] + p] = src[i];
    }
}

// ---------------------------------------------------------------------------
// Aggregation: mean of neighbor features. 16 threads per node, float4 each.
__global__ __launch_bounds__(256) void k_agg(const float* __restrict__ x,
                                             float* __restrict__ meanout, int n) {
    int t = blockIdx.x * blockDim.x + threadIdx.x;
    int node = t >> 4;
    int c = t & 15;
    if (node >= n) return;
    int base = g_rowstart[node];
    int dg = g_deg[node];
    const float4* xv = (const float4*)x;
    float4 acc = make_float4(0.f, 0.f, 0.f, 0.f);
    for (int k = 0; k < dg; k++) {
        int s = __ldg(&g_csr[base + k]);
        float4 v = __ldg(&xv[(size_t)s * 16 + c]);
        acc.x += v.x; acc.y += v.y; acc.z += v.z; acc.w += v.w;
    }
    float invd = 1.0f / (float)max(dg, 1);
    acc.x *= invd; acc.y *= invd; acc.z *= invd; acc.w *= invd;
    ((float4*)meanout)[(size_t)node * 16 + c] = acc;
}

// ---------------------------------------------------------------------------
// Fused: out = relu(l2norm(mean @ Wl^T + bl + x @ Wr^T))
// Block: 256 threads, NT=32 nodes. tid&31 = node lane, tid>>5 = output group (8 outs each).
__global__ __launch_bounds__(256) void k_gemm(const float* __restrict__ mean,
                                              const float* __restrict__ xin,
                                              const float* __restrict__ Wl,
                                              const float* __restrict__ bl,
                                              const float* __restrict__ Wr,
                                              float* __restrict__ out, int n) {
    __shared__ float w_s[KK][DF];      // 32 KB, [k][o], transposed weights
    __shared__ float z_s[KK * NT];     // 16 KB, [k][node]; reused for sq reduce
    int tid = threadIdx.x;
    // load weights transposed: w_s[k][o] = Wl[o*64+k]; w_s[64+k][o] = Wr[o*64+k]
    for (int i = tid; i < DF * DF; i += 256) {
        int o = i >> 6, k = i & 63;
        w_s[k][o] = Wl[i];
        w_s[DF + k][o] = Wr[i];
    }
    int nodeBase = blockIdx.x * NT;
    int nl = tid & 31;
    int og = tid >> 5;
    int node = nodeBase + nl;
    bool valid = node < n;
    // load z tile transposed: z_s[k*NT + n] ; k = og*4 + c*32 covers all mult-of-4
    {
        int gn = nodeBase + nl;
#pragma unroll
        for (int c = 0; c < 4; c++) {
            int k0 = og * 4 + c * 32;
            float4 v = make_float4(0.f, 0.f, 0.f, 0.f);
            if (gn < n) {
                const float* p = (k0 < DF) ? (mean + (size_t)gn * DF + k0)
                                           : (xin + (size_t)gn * DF + (k0 - DF));
                v = *(const float4*)p;
            }
            z_s[(k0 + 0) * NT + nl] = v.x;
            z_s[(k0 + 1) * NT + nl] = v.y;
            z_s[(k0 + 2) * NT + nl] = v.z;
            z_s[(k0 + 3) * NT + nl] = v.w;
        }
    }
    __syncthreads();

    float acc[8];
    {
        float4 b0 = *(const float4*)(bl + og * 8);
        float4 b1 = *(const float4*)(bl + og * 8 + 4);
        acc[0] = b0.x; acc[1] = b0.y; acc[2] = b0.z; acc[3] = b0.w;
        acc[4] = b1.x; acc[5] = b1.y; acc[6] = b1.z; acc[7] = b1.w;
    }
#pragma unroll 8
    for (int k = 0; k < KK; k++) {
        float zv = z_s[k * NT + nl];
        const float4* wp = (const float4*)&w_s[k][og * 8];
        float4 w0 = wp[0], w1 = wp[1];
        acc[0] += zv * w0.x; acc[1] += zv * w0.y;
        acc[2] += zv * w0.z; acc[3] += zv * w0.w;
        acc[4] += zv * w1.x; acc[5] += zv * w1.y;
        acc[6] += zv * w1.z; acc[7] += zv * w1.w;
    }
    float sq = 0.f;
#pragma unroll
    for (int j = 0; j < 8; j++) sq += acc[j] * acc[j];
    __syncthreads();                 // everyone done reading z_s
    z_s[og * NT + nl] = sq;          // reuse z_s as [8][32] sq buffer
    __syncthreads();
    float tot = 0.f;
#pragma unroll
    for (int j = 0; j < 8; j++) tot += z_s[j * NT + nl];
    float nrm = sqrtf(tot);
    float scale = 1.0f / fmaxf(nrm, 1e-12f);
    if (valid) {
        float4 o0, o1;
        o0.x = fmaxf(acc[0] * scale, 0.f); o0.y = fmaxf(acc[1] * scale, 0.f);
        o0.z = fmaxf(acc[2] * scale, 0.f); o0.w = fmaxf(acc[3] * scale, 0.f);
        o1.x = fmaxf(acc[4] * scale, 0.f); o1.y = fmaxf(acc[5] * scale, 0.f);
        o1.z = fmaxf(acc[6] * scale, 0.f); o1.w = fmaxf(acc[7] * scale, 0.f);
        float4* op = (float4*)(out + (size_t)node * DF + og * 8);
        op[0] = o0; op[1] = o1;
    }
}

// ---------------------------------------------------------------------------
__device__ __forceinline__ int lower_bound_i(const int* __restrict__ a, int n, int v) {
    int lo = 0, hi = n;
    while (lo < hi) {
        int m = (lo + hi) >> 1;
        if (a[m] < v) lo = m + 1; else hi = m;
    }
    return lo;
}

// Sum-pool per graph. batch is sorted; block b handles graph b.
__global__ __launch_bounds__(256) void k_pool(const float* __restrict__ h,
                                              const int* __restrict__ batch,
                                              float* __restrict__ out, int n) {
    __shared__ int s_lo, s_hi;
    __shared__ float red[4][DF];
    int b = blockIdx.x;
    if (threadIdx.x == 0) {
        s_lo = lower_bound_i(batch, n, b);
        s_hi = lower_bound_i(batch, n, b + 1);
    }
    __syncthreads();
    int lo = s_lo, hi = s_hi;
    int f = threadIdx.x & 63;
    int lane = threadIdx.x >> 6;   // 0..3
    float acc = 0.f;
    for (int nd = lo + lane; nd < hi; nd += 4)
        acc += h[(size_t)nd * DF + f];
    red[lane][f] = acc;
    __syncthreads();
    if (lane == 0)
        out[b * DF + f] = red[0][f] + red[1][f] + red[2][f] + red[3][f];
}

// ---------------------------------------------------------------------------
extern "C" void kernel_launch(void* const* d_in, const int* in_sizes, int n_in,
                              void* d_out, int out_size) {
    const float* x_raw = (const float*)d_in[0];
    const int*   ei    = (const int*)d_in[1];
    const int*   batch = (const int*)d_in[2];
    const float* W[9];
    for (int i = 0; i < 9; i++) W[i] = (const float*)d_in[3 + i];
    // W layout: [Wl0, bl0, Wr0, Wl1, bl1, Wr1, Wl2, bl2, Wr2]

    int n = in_sizes[0] / DF;      // 100000
    int e = in_sizes[1] / 2;       // 1600000
    int b = out_size / DF;         // 64
    const int* src = ei;
    const int* dst = ei + e;

    float* out = (float*)d_out;

    int nblk = (n + SCAN_CHUNK - 1) / SCAN_CHUNK;

    // ---- CSR build (once per launch) ----
    k_zero<<<(n + 255) / 256, 256>>>(n);
    k_hist<<<(e + 255) / 256, 256>>>(dst, e);
    k_blocksum<<<nblk, 256>>>(n);
    k_scan_bsums<<<1, 32>>>(nblk);
    k_scan_final<<<nblk, 256>>>(n);
    k_fill<<<(e + 255) / 256, 256>>>(src, dst, e);

    float* mean; cudaGetSymbolAddress((void**)&mean, g_mean);
    float* h1;   cudaGetSymbolAddress((void**)&h1, g_h1);
    float* h2;   cudaGetSymbolAddress((void**)&h2, g_h2);

    int aggGrid  = (n * 16 + 255) / 256;
    int gemmGrid = (n + NT - 1) / NT;

    // layer 0: x_raw -> h1
    k_agg<<<aggGrid, 256>>>(x_raw, mean, n);
    k_gemm<<<gemmGrid, 256>>>(mean, x_raw, W[0], W[1], W[2], h1, n);
    // layer 1: h1 -> h2
    k_agg<<<aggGrid, 256>>>(h1, mean, n);
    k_gemm<<<gemmGrid, 256>>>(mean, h1, W[3], W[4], W[5], h2, n);
    // layer 2: h2 -> h1
    k_agg<<<aggGrid, 256>>>(h2, mean, n);
    k_gemm<<<gemmGrid, 256>>>(mean, h2, W[6], W[7], W[8], h1, n);

    // readout
    k_pool<<<b, 256>>>(h1, batch, out, n);
}

// round 2
// speedup vs baseline: 1.5103x; 1.5103x over previous
#include <cuda_runtime.h>
#include <cuda_bf16.h>
#include <stdint.h>

// ============================================================================
// LocalGNNBranch: 3-layer GraphSAGE, N=100k, E=1.6M, D=64, B=64. All fp32.
//  - CSR build once per launch (int atomics only, parallel scan)
//  - 3x [gather-mean aggregation (MLP=4 unrolled) -> fused FFMA2 GEMM
//        + bias + L2norm + ReLU]
//  - sum-pool readout via binary search on sorted batch ids
// GEMM uses packed fma.rn.f32x2 (2 FMA/instr) -> 128 FMA-lanes/cyc/SM.
// ============================================================================

#define MAXN 100000
#define MAXE 1600000
#define DF   64
#define KK   128         // GEMM K = 2*DF (mean || x)
#define NT   128         // nodes per GEMM block
#define WS   66          // w_s row stride (floats), 2-way-conflict max, 8B aligned rows
#define ZS   130         // z_s row stride (floats), conflict-free scalar reads
#define SCAN_CHUNK 1024
#define MAXBLK 128

typedef unsigned long long ull;

// ---- static device scratch (no allocation allowed) ----
__device__ float g_mean[(size_t)MAXN * DF];
__device__ float g_h1[(size_t)MAXN * DF];
__device__ float g_h2[(size_t)MAXN * DF];
__device__ int   g_deg[MAXN];
__device__ int   g_rowstart[MAXN];
__device__ int   g_cursor[MAXN];
__device__ int   g_csr[MAXE];
__device__ int   g_bsum[MAXBLK];
__device__ int   g_bsumex[MAXBLK];

// ---- f32x2 helpers ----
__device__ __forceinline__ ull pk2(float lo, float hi) {
    ull r; asm("mov.b64 %0, {%1, %2};" : "=l"(r) : "f"(lo), "f"(hi)); return r;
}
__device__ __forceinline__ void fma2(ull& d, ull a, ull b) {
    asm("fma.rn.f32x2 %0, %1, %2, %0;" : "+l"(d) : "l"(a), "l"(b));
}
__device__ __forceinline__ float2 up2(ull v) {
    float2 f; asm("mov.b64 {%0, %1}, %2;" : "=f"(f.x), "=f"(f.y) : "l"(v)); return f;
}

// ---------------------------------------------------------------------------
__global__ void k_zero(int n) {
    int i = blockIdx.x * blockDim.x + threadIdx.x;
    if (i < n) { g_deg[i] = 0; g_cursor[i] = 0; }
}

__global__ void k_hist(const int* __restrict__ dst, int e) {
    int i = blockIdx.x * blockDim.x + threadIdx.x;
    if (i < e) atomicAdd(&g_deg[dst[i]], 1);
}

__global__ void k_blocksum(int n) {
    __shared__ int s[256];
    int tid = threadIdx.x;
    int start = blockIdx.x * SCAN_CHUNK;
    int end = min(start + SCAN_CHUNK, n);
    int sum = 0;
    for (int i = start + tid; i < end; i += 256) sum += g_deg[i];
    s[tid] = sum;
    __syncthreads();
    for (int d = 128; d > 0; d >>= 1) {
        if (tid < d) s[tid] += s[tid + d];
        __syncthreads();
    }
    if (tid == 0) g_bsum[blockIdx.x] = s[0];
}

// parallel exclusive scan over up to 128 block sums
__global__ void k_scan_bsums(int nblk) {
    __shared__ int s[128];
    int tid = threadIdx.x;
    int v = (tid < nblk) ? g_bsum[tid] : 0;
    s[tid] = v;
    __syncthreads();
    for (int d = 1; d < 128; d <<= 1) {
        int t = (tid >= d) ? s[tid - d] : 0;
        __syncthreads();
        s[tid] += t;
        __syncthreads();
    }
    if (tid < nblk) g_bsumex[tid] = s[tid] - v;
}

__global__ void k_scan_final(int n) {
    __shared__ int s[256];
    int tid = threadIdx.x;
    int b = blockIdx.x;
    int base = b * SCAN_CHUNK + tid * 4;
    int v[4];
    int tsum = 0;
#pragma unroll
    for (int i = 0; i < 4; i++) {
        int gi = base + i;
        v[i] = (gi < n) ? g_deg[gi] : 0;
        tsum += v[i];
    }
    s[tid] = tsum;
    __syncthreads();
    for (int d = 1; d < 256; d <<= 1) {
        int t = (tid >= d) ? s[tid - d] : 0;
        __syncthreads();
        s[tid] += t;
        __syncthreads();
    }
    int excl = s[tid] - tsum;
    int run = g_bsumex[b] + excl;
#pragma unroll
    for (int i = 0; i < 4; i++) {
        int gi = base + i;
        if (gi < n) { g_rowstart[gi] = run; run += v[i]; }
    }
}

__global__ void k_fill(const int* __restrict__ src, const int* __restrict__ dst, int e) {
    int i = blockIdx.x * blockDim.x + threadIdx.x;
    if (i < e) {
        int d = dst[i];
        int p = atomicAdd(&g_cursor[d], 1);
        g_csr[g_rowstart[d] + p] = src[i];
    }
}

// ---------------------------------------------------------------------------
// Aggregation: mean of neighbor features. 16 threads/node, float4 each.
// Unrolled x4: 4 independent index loads + 4 independent gathers (MLP=4).
__global__ __launch_bounds__(256) void k_agg(const float* __restrict__ x,
                                             float* __restrict__ meanout, int n) {
    int t = blockIdx.x * blockDim.x + threadIdx.x;
    int node = t >> 4;
    int c = t & 15;
    if (node >= n) return;
    int base = g_rowstart[node];
    int dg = g_deg[node];
    const float4* xv = (const float4*)x;
    float4 a0 = make_float4(0.f, 0.f, 0.f, 0.f);
    float4 a1 = a0, a2 = a0, a3 = a0;
    int k = 0;
    for (; k + 4 <= dg; k += 4) {
        int s0 = __ldg(&g_csr[base + k + 0]);
        int s1 = __ldg(&g_csr[base + k + 1]);
        int s2 = __ldg(&g_csr[base + k + 2]);
        int s3 = __ldg(&g_csr[base + k + 3]);
        float4 v0 = __ldg(&xv[(size_t)s0 * 16 + c]);
        float4 v1 = __ldg(&xv[(size_t)s1 * 16 + c]);
        float4 v2 = __ldg(&xv[(size_t)s2 * 16 + c]);
        float4 v3 = __ldg(&xv[(size_t)s3 * 16 + c]);
        a0.x += v0.x; a0.y += v0.y; a0.z += v0.z; a0.w += v0.w;
        a1.x += v1.x; a1.y += v1.y; a1.z += v1.z; a1.w += v1.w;
        a2.x += v2.x; a2.y += v2.y; a2.z += v2.z; a2.w += v2.w;
        a3.x += v3.x; a3.y += v3.y; a3.z += v3.z; a3.w += v3.w;
    }
    for (; k < dg; k++) {
        int s = __ldg(&g_csr[base + k]);
        float4 v = __ldg(&xv[(size_t)s * 16 + c]);
        a0.x += v.x; a0.y += v.y; a0.z += v.z; a0.w += v.w;
    }
    float4 acc;
    acc.x = (a0.x + a1.x) + (a2.x + a3.x);
    acc.y = (a0.y + a1.y) + (a2.y + a3.y);
    acc.z = (a0.z + a1.z) + (a2.z + a3.z);
    acc.w = (a0.w + a1.w) + (a2.w + a3.w);
    float invd = 1.0f / (float)max(dg, 1);
    acc.x *= invd; acc.y *= invd; acc.z *= invd; acc.w *= invd;
    ((float4*)meanout)[(size_t)node * 16 + c] = acc;
}

// ---------------------------------------------------------------------------
// Fused GEMM: out = relu(l2norm([mean||x] @ [Wl;Wr]^T + bl))
// 256 threads, 128 nodes x 64 outs per block. Each thread: 4 nodes x 8 outs,
// inner product via packed fma.rn.f32x2 (16 FFMA2 per k).
__global__ __launch_bounds__(256, 2) void k_gemm(const float* __restrict__ mean,
                                                 const float* __restrict__ xin,
                                                 const float* __restrict__ Wl,
                                                 const float* __restrict__ bl,
                                                 const float* __restrict__ Wr,
                                                 float* __restrict__ out, int n) {
    extern __shared__ float smem[];
    float* w_s = smem;              // [KK][WS]  transposed weights: w_s[k*WS+o]
    float* z_s = smem + KK * WS;    // [NT][ZS]  z tile: z_s[node*ZS+k]
    int tid = threadIdx.x;

    // weights (gmem-coalesced read, 2-way-conflict STS)
    for (int i = tid; i < DF * DF; i += 256) {
        int o = i >> 6, k = i & 63;
        w_s[k * WS + o]        = Wl[i];   // Wl[o*64+k]
        w_s[(k + DF) * WS + o] = Wr[i];
    }
    int nodeBase = blockIdx.x * NT;
    // z tile [node][k]: k<64 = mean row, k>=64 = x row. Coalesced float4 reads.
    for (int i = tid; i < NT * 32; i += 256) {
        int nl = i >> 5, c = i & 31;
        int gn = nodeBase + nl;
        float4 v = make_float4(0.f, 0.f, 0.f, 0.f);
        if (gn < n) {
            const float4* p = (c < 16)
                ? ((const float4*)(mean + (size_t)gn * DF) + c)
                : ((const float4*)(xin + (size_t)gn * DF) + (c - 16));
            v = __ldg(p);
        }
        float* zp = z_s + nl * ZS + c * 4;
        zp[0] = v.x; zp[1] = v.y; zp[2] = v.z; zp[3] = v.w;
    }
    __syncthreads();

    int og = tid & 7;       // output group: outs og*8 .. og*8+7
    int ng = tid >> 3;      // node group: nodes ng*4 .. ng*4+3
    int nrow = ng * 4;

    const float* bp = bl + og * 8;
    ull acc[4][4];
    {
        ull b0 = pk2(bp[0], bp[1]), b1 = pk2(bp[2], bp[3]);
        ull b2 = pk2(bp[4], bp[5]), b3 = pk2(bp[6], bp[7]);
#pragma unroll
        for (int nn = 0; nn < 4; nn++) {
            acc[nn][0] = b0; acc[nn][1] = b1; acc[nn][2] = b2; acc[nn][3] = b3;
        }
    }

    const float* zb = z_s + nrow * ZS;
    const float* wb = w_s + og * 8;
#pragma unroll 4
    for (int k = 0; k < KK; k++) {
        ull zz0 = pk2(zb[0 * ZS + k], zb[0 * ZS + k]);
        ull zz1 = pk2(zb[1 * ZS + k], zb[1 * ZS + k]);
        ull zz2 = pk2(zb[2 * ZS + k], zb[2 * ZS + k]);
        ull zz3 = pk2(zb[3 * ZS + k], zb[3 * ZS + k]);
        const float* wr_ = wb + k * WS;
        ull w0 = *(const ull*)(wr_ + 0);
        ull w1 = *(const ull*)(wr_ + 2);
        ull w2 = *(const ull*)(wr_ + 4);
        ull w3 = *(const ull*)(wr_ + 6);
        fma2(acc[0][0], zz0, w0); fma2(acc[0][1], zz0, w1);
        fma2(acc[0][2], zz0, w2); fma2(acc[0][3], zz0, w3);
        fma2(acc[1][0], zz1, w0); fma2(acc[1][1], zz1, w1);
        fma2(acc[1][2], zz1, w2); fma2(acc[1][3], zz1, w3);
        fma2(acc[2][0], zz2, w0); fma2(acc[2][1], zz2, w1);
        fma2(acc[2][2], zz2, w2); fma2(acc[2][3], zz2, w3);
        fma2(acc[3][0], zz3, w0); fma2(acc[3][1], zz3, w1);
        fma2(acc[3][2], zz3, w2); fma2(acc[3][3], zz3, w3);
    }

    // epilogue: per-node L2 norm across the 8 og-lanes (8 consecutive lanes
    // share ng), then ReLU + store.
#pragma unroll
    for (int nn = 0; nn < 4; nn++) {
        float2 f0 = up2(acc[nn][0]), f1 = up2(acc[nn][1]);
        float2 f2 = up2(acc[nn][2]), f3 = up2(acc[nn][3]);
        float sq = f0.x * f0.x + f0.y * f0.y + f1.x * f1.x + f1.y * f1.y
                 + f2.x * f2.x + f2.y * f2.y + f3.x * f3.x + f3.y * f3.y;
        sq += __shfl_xor_sync(0xffffffffu, sq, 1);
        sq += __shfl_xor_sync(0xffffffffu, sq, 2);
        sq += __shfl_xor_sync(0xffffffffu, sq, 4);
        float scale = 1.0f / fmaxf(sqrtf(sq), 1e-12f);
        int node = nodeBase + nrow + nn;
        if (node < n) {
            float4 o0 = make_float4(fmaxf(f0.x * scale, 0.f), fmaxf(f0.y * scale, 0.f),
                                    fmaxf(f1.x * scale, 0.f), fmaxf(f1.y * scale, 0.f));
            float4 o1 = make_float4(fmaxf(f2.x * scale, 0.f), fmaxf(f2.y * scale, 0.f),
                                    fmaxf(f3.x * scale, 0.f), fmaxf(f3.y * scale, 0.f));
            float4* op = (float4*)(out + (size_t)node * DF + og * 8);
            op[0] = o0; op[1] = o1;
        }
    }
}

// ---------------------------------------------------------------------------
__device__ __forceinline__ int lower_bound_i(const int* __restrict__ a, int n, int v) {
    int lo = 0, hi = n;
    while (lo < hi) {
        int m = (lo + hi) >> 1;
        if (a[m] < v) lo = m + 1; else hi = m;
    }
    return lo;
}

__global__ __launch_bounds__(256) void k_pool(const float* __restrict__ h,
                                              const int* __restrict__ batch,
                                              float* __restrict__ out, int n) {
    __shared__ int s_lo, s_hi;
    __shared__ float red[4][DF];
    int b = blockIdx.x;
    if (threadIdx.x == 0) {
        s_lo = lower_bound_i(batch, n, b);
        s_hi = lower_bound_i(batch, n, b + 1);
    }
    __syncthreads();
    int lo = s_lo, hi = s_hi;
    int f = threadIdx.x & 63;
    int lane = threadIdx.x >> 6;
    float acc = 0.f;
    for (int nd = lo + lane; nd < hi; nd += 4)
        acc += h[(size_t)nd * DF + f];
    red[lane][f] = acc;
    __syncthreads();
    if (lane == 0)
        out[b * DF + f] = red[0][f] + red[1][f] + red[2][f] + red[3][f];
}

// ---------------------------------------------------------------------------
extern "C" void kernel_launch(void* const* d_in, const int* in_sizes, int n_in,
                              void* d_out, int out_size) {
    const float* x_raw = (const float*)d_in[0];
    const int*   ei    = (const int*)d_in[1];
    const int*   batch = (const int*)d_in[2];
    const float* W[9];
    for (int i = 0; i < 9; i++) W[i] = (const float*)d_in[3 + i];

    int n = in_sizes[0] / DF;
    int e = in_sizes[1] / 2;
    int b = out_size / DF;
    const int* src = ei;
    const int* dst = ei + e;
    float* out = (float*)d_out;

    int nblk = (n + SCAN_CHUNK - 1) / SCAN_CHUNK;

    static int smem_set = 0;
    const int GEMM_SMEM = (KK * WS + NT * ZS) * 4;   // 100352 bytes
    if (!smem_set) {
        cudaFuncSetAttribute(k_gemm, cudaFuncAttributeMaxDynamicSharedMemorySize,
                             GEMM_SMEM);
        smem_set = 1;
    }

    // ---- CSR build ----
    k_zero<<<(n + 255) / 256, 256>>>(n);
    k_hist<<<(e + 255) / 256, 256>>>(dst, e);
    k_blocksum<<<nblk, 256>>>(n);
    k_scan_bsums<<<1, 128>>>(nblk);
    k_scan_final<<<nblk, 256>>>(n);
    k_fill<<<(e + 255) / 256, 256>>>(src, dst, e);

    float* mean; cudaGetSymbolAddress((void**)&mean, g_mean);
    float* h1;   cudaGetSymbolAddress((void**)&h1, g_h1);
    float* h2;   cudaGetSymbolAddress((void**)&h2, g_h2);

    int aggGrid  = (n * 16 + 255) / 256;
    int gemmGrid = (n + NT - 1) / NT;

    k_agg<<<aggGrid, 256>>>(x_raw, mean, n);
    k_gemm<<<gemmGrid, 256, GEMM_SMEM>>>(mean, x_raw, W[0], W[1], W[2], h1, n);
    k_agg<<<aggGrid, 256>>>(h1, mean, n);
    k_gemm<<<gemmGrid, 256, GEMM_SMEM>>>(mean, h1, W[3], W[4], W[5], h2, n);
    k_agg<<<aggGrid, 256>>>(h2, mean, n);
    k_gemm<<<gemmGrid, 256, GEMM_SMEM>>>(mean, h2, W[6], W[7], W[8], h1, n);

    k_pool<<<b, 256>>>(h1, batch, out, n);
}